// round 11
// baseline (speedup 1.0000x reference)
#include <cuda_runtime.h>
#include <cuda_bf16.h>
#include <math.h>

#define NN 8192
#define DD 256
#define DA 64

// ---------------- scratch (device globals; no allocations allowed) -------------
__device__ float g_L[(size_t)NN * NN];        // logits / A (in place)
__device__ float g_q[NN * DA];
__device__ float g_k[NN * DA];
__device__ float g_t[NN * DA];
__device__ float g_Xf[NN * DD];
__device__ float g_Xf2[NN * DD];
__device__ float g_Xa[NN * DD];
__device__ float g_Xa2[NN * DD];
__device__ float g_Z[NN * DD];
__device__ float g_rinv[NN];

// ---------------- block reductions (256 threads, broadcast result) -------------
__device__ __forceinline__ float blk_sum(float x, float* sm) {
    #pragma unroll
    for (int o = 16; o > 0; o >>= 1) x += __shfl_xor_sync(0xffffffffu, x, o);
    int w = threadIdx.x >> 5;
    __syncthreads();
    if ((threadIdx.x & 31) == 0) sm[w] = x;
    __syncthreads();
    float r = 0.f;
    #pragma unroll
    for (int i = 0; i < 8; i++) r += sm[i];
    return r;
}

__device__ __forceinline__ float blk_max(float x, float* sm) {
    #pragma unroll
    for (int o = 16; o > 0; o >>= 1) x = fmaxf(x, __shfl_xor_sync(0xffffffffu, x, o));
    int w = threadIdx.x >> 5;
    __syncthreads();
    if ((threadIdx.x & 31) == 0) sm[w] = x;
    __syncthreads();
    float r = -INFINITY;
    #pragma unroll
    for (int i = 0; i < 8; i++) r = fmaxf(r, sm[i]);
    return r;
}

__device__ __forceinline__ double blk_sum_d(double x, double* smd) {
    #pragma unroll
    for (int o = 16; o > 0; o >>= 1) x += __shfl_xor_sync(0xffffffffu, x, o);
    int w = threadIdx.x >> 5;
    __syncthreads();
    if ((threadIdx.x & 31) == 0) smd[w] = x;
    __syncthreads();
    double r = 0.0;
    #pragma unroll
    for (int i = 0; i < 8; i++) r += smd[i];
    return r;
}

// ---------------- row sums of S -> rinv = 1/(1 + sum) --------------------------
__global__ void rowsum_kernel(const float* __restrict__ S, float* __restrict__ rinv) {
    __shared__ float sm[8];
    int row = blockIdx.x;
    const float* Sr = S + (size_t)row * NN;
    float s = 0.f;
    for (int j = threadIdx.x; j < NN; j += 256) s += Sr[j];
    s = blk_sum(s, sm);
    if (threadIdx.x == 0) rinv[row] = 1.0f / (s + 1.0f);
}

// ---------------- fp32 SIMT GEMM, C[M,N] = A[M,K] * op(B) ----------------------
// TRANSB=1: B is [N,K] row-major (NT).  TRANSB=0: B is [K,N] row-major (NN).
// EPI: 0 -> C = acc ; 1 -> C = rscale[row]*(acc + Xadd[row,col]) ; 2 -> C += acc
#define BM 128
#define BN 128
#define BK 16
#define SPAD 4

template<int TRANSB, int EPI>
__global__ void __launch_bounds__(256) gemm_kernel(
    const float* __restrict__ A, const float* __restrict__ B, float* __restrict__ C,
    int M, int N, int K,
    const float* __restrict__ Xadd, const float* __restrict__ rscale)
{
    __shared__ float As[BK][BM + SPAD];
    __shared__ float Bs[BK][BN + SPAD];

    const int tid = threadIdx.x;
    const int m0 = blockIdx.y * BM;
    const int n0 = blockIdx.x * BN;
    const int tx = tid & 15;
    const int ty = tid >> 4;

    float acc[8][8];
    #pragma unroll
    for (int i = 0; i < 8; i++)
        #pragma unroll
        for (int j = 0; j < 8; j++) acc[i][j] = 0.f;

    for (int k0 = 0; k0 < K; k0 += BK) {
        #pragma unroll
        for (int it = 0; it < 2; it++) {
            int r = (tid >> 2) + it * 64;
            int c = (tid & 3) * 4;
            float4 v = *(const float4*)(A + (size_t)(m0 + r) * K + k0 + c);
            As[c + 0][r] = v.x; As[c + 1][r] = v.y; As[c + 2][r] = v.z; As[c + 3][r] = v.w;
        }
        if (TRANSB) {
            #pragma unroll
            for (int it = 0; it < 2; it++) {
                int r = (tid >> 2) + it * 64;   // n index
                int c = (tid & 3) * 4;          // k index
                float4 v = make_float4(0.f, 0.f, 0.f, 0.f);
                if (n0 + r < N) v = *(const float4*)(B + (size_t)(n0 + r) * K + k0 + c);
                Bs[c + 0][r] = v.x; Bs[c + 1][r] = v.y; Bs[c + 2][r] = v.z; Bs[c + 3][r] = v.w;
            }
        } else {
            #pragma unroll
            for (int it = 0; it < 2; it++) {
                int r = (tid >> 5) + it * 8;    // k index
                int c = (tid & 31) * 4;         // n index
                float4 v = make_float4(0.f, 0.f, 0.f, 0.f);
                if (n0 + c < N) v = *(const float4*)(B + (size_t)(k0 + r) * N + n0 + c);
                *(float4*)&Bs[r][c] = v;
            }
        }
        __syncthreads();

        #pragma unroll
        for (int k = 0; k < BK; k++) {
            float a[8], b[8];
            *(float4*)&a[0] = *(const float4*)&As[k][ty * 8];
            *(float4*)&a[4] = *(const float4*)&As[k][ty * 8 + 4];
            *(float4*)&b[0] = *(const float4*)&Bs[k][tx * 8];
            *(float4*)&b[4] = *(const float4*)&Bs[k][tx * 8 + 4];
            #pragma unroll
            for (int i = 0; i < 8; i++)
                #pragma unroll
                for (int j = 0; j < 8; j++)
                    acc[i][j] = fmaf(a[i], b[j], acc[i][j]);
        }
        __syncthreads();
    }

    #pragma unroll
    for (int i = 0; i < 8; i++) {
        int row = m0 + ty * 8 + i;
        float rs = (EPI == 1) ? rscale[row] : 0.f;
        #pragma unroll
        for (int jj = 0; jj < 2; jj++) {
            int col = n0 + tx * 8 + jj * 4;
            if (col < N) {
                size_t idx = (size_t)row * N + col;
                float4 v;
                v.x = acc[i][jj * 4 + 0]; v.y = acc[i][jj * 4 + 1];
                v.z = acc[i][jj * 4 + 2]; v.w = acc[i][jj * 4 + 3];
                if (EPI == 1) {
                    float4 ad = *(const float4*)(Xadd + idx);
                    v.x = rs * (v.x + ad.x); v.y = rs * (v.y + ad.y);
                    v.z = rs * (v.z + ad.z); v.w = rs * (v.w + ad.w);
                } else if (EPI == 2) {
                    float4 cv = *(const float4*)(C + idx);
                    v.x += cv.x; v.y += cv.y; v.z += cv.z; v.w += cv.w;
                }
                *(float4*)(C + idx) = v;
            }
        }
    }
}

// ---------------- top-p: LITERAL replication of the reference ------------------
// Per row: softmax probs (fp32 division), full descending sort with ascending-
// index tie-break (bitonic on u64 keys = [prob bits | ~index]), then a bitwise
// sequential fp32 cumsum walk: cs = fl(cs+p); excl = fl(cs-p); keep while
// excl < 0.9f (includes the crossing element; monotone -> early exit).
// Then A_i = p_i * (1/kept_sum) scattered back; all else zero.
__global__ void __launch_bounds__(256) topp_kernel(float* __restrict__ L) {
    extern __shared__ unsigned long long key[];   // 8192 keys = 64KB
    __shared__ float sm[8];
    __shared__ double smd[8];
    __shared__ int s_jstop;
    __shared__ float s_inv;

    const int row = blockIdx.x;
    const int tid = threadIdx.x;
    float* Lr = L + (size_t)row * NN;

    float v[32];
    #pragma unroll
    for (int i = 0; i < 32; i++) v[i] = Lr[i * 256 + tid];

    float m = -INFINITY;
    #pragma unroll
    for (int i = 0; i < 32; i++) m = fmaxf(m, v[i]);
    m = blk_max(m, sm);

    // e-values with correctly-rounded exp (double-internal)
    double zloc = 0.0;
    #pragma unroll
    for (int i = 0; i < 32; i++) {
        v[i] = (float)exp((double)(v[i] - m));
        zloc += (double)v[i];
    }
    double Zd = blk_sum_d(zloc, smd);
    const float Zf = (float)Zd;

    // probs (fp32 division, like the reference softmax) + sort keys
    #pragma unroll
    for (int i = 0; i < 32; i++) {
        int idx = i * 256 + tid;
        float p = __fdiv_rn(v[i], Zf);
        v[i] = p;
        key[idx] = ((unsigned long long)__float_as_uint(p) << 32)
                 | (unsigned long long)(0xFFFFFFFFu - (unsigned)idx);
    }
    __syncthreads();

    // bitonic sort, DESCENDING by u64 key (probs are >= 0 so bit order = value
    // order; unique low bits make keys distinct and give ascending-index ties)
    for (int k = 2; k <= NN; k <<= 1) {
        for (int j = k >> 1; j > 0; j >>= 1) {
            #pragma unroll 4
            for (int base = 0; base < NN; base += 256) {
                int i = base + tid;
                int ij = i ^ j;
                if (ij > i) {
                    unsigned long long a = key[i];
                    unsigned long long b = key[ij];
                    bool descBlock = ((i & k) == 0);
                    // descending final order: flip canonical ascending network
                    if (descBlock ? (a < b) : (a > b)) {
                        key[i] = b;
                        key[ij] = a;
                    }
                }
            }
            __syncthreads();
        }
    }

    // sequential fp32 cumsum walk (bitwise-faithful to the reference), early exit
    if (tid == 0) {
        float cs = 0.f;
        int j = 0;
        for (; j < NN; j++) {
            float p = __uint_as_float((unsigned)(key[j] >> 32));
            cs = __fadd_rn(cs, p);
            float excl = __fsub_rn(cs, p);
            if (!(excl < 0.9f)) break;     // first dropped position
        }
        s_jstop = j;                        // kept = sorted positions [0, j)
    }
    __syncthreads();
    const int jstop = s_jstop;

    // kept mass (double) -> inv
    {
        double ks = 0.0;
        for (int p0 = tid; p0 < jstop; p0 += 256)
            ks += (double)__uint_as_float((unsigned)(key[p0] >> 32));
        double ksd = blk_sum_d(ks, smd);
        if (tid == 0) s_inv = (float)(1.0 / fmax(ksd, 1e-12));
    }
    __syncthreads();
    const float inv = s_inv;

    // zero the row, then scatter kept entries
    #pragma unroll
    for (int i = 0; i < 32; i++) Lr[i * 256 + tid] = 0.f;
    __syncthreads();
    for (int p0 = tid; p0 < jstop; p0 += 256) {
        unsigned long long kk = key[p0];
        unsigned orig = 0xFFFFFFFFu - (unsigned)(kk & 0xFFFFFFFFull);
        float p = __uint_as_float((unsigned)(kk >> 32));
        Lr[orig] = p * inv;
    }
}

// ---------------- final residual + layernorm -----------------------------------
__global__ void __launch_bounds__(256) ln_kernel(
    const float* __restrict__ X, const float* __restrict__ Z,
    const float* __restrict__ g, const float* __restrict__ b,
    float* __restrict__ out)
{
    __shared__ float sm[8];
    int row = blockIdx.x;
    int c = threadIdx.x;
    size_t idx = (size_t)row * DD + c;
    float h = X[idx] + Z[idx];
    float s1 = blk_sum(h, sm);
    float mu = s1 * (1.0f / DD);
    float d = h - mu;
    float s2 = blk_sum(d * d, sm);
    float var = s2 * (1.0f / DD);
    out[idx] = d * rsqrtf(var + 1e-5f) * g[c] + b[c];
}

// ---------------- host orchestration -------------------------------------------
extern "C" void kernel_launch(void* const* d_in, const int* in_sizes, int n_in,
                              void* d_out, int out_size) {
    const float* X   = (const float*)d_in[0];
    const float* S   = (const float*)d_in[1];
    const float* W1  = (const float*)d_in[2];
    const float* W2  = (const float*)d_in[3];
    const float* W3  = (const float*)d_in[4];
    const float* U1  = (const float*)d_in[5];
    const float* U2  = (const float*)d_in[6];
    const float* lng = (const float*)d_in[7];
    const float* lnb = (const float*)d_in[8];
    float* out = (float*)d_out;

    float *L, *q, *k, *t, *Xf, *Xf2, *Xa, *Xa2, *Z, *rinv;
    cudaGetSymbolAddress((void**)&L,    g_L);
    cudaGetSymbolAddress((void**)&q,    g_q);
    cudaGetSymbolAddress((void**)&k,    g_k);
    cudaGetSymbolAddress((void**)&t,    g_t);
    cudaGetSymbolAddress((void**)&Xf,   g_Xf);
    cudaGetSymbolAddress((void**)&Xf2,  g_Xf2);
    cudaGetSymbolAddress((void**)&Xa,   g_Xa);
    cudaGetSymbolAddress((void**)&Xa2,  g_Xa2);
    cudaGetSymbolAddress((void**)&Z,    g_Z);
    cudaGetSymbolAddress((void**)&rinv, g_rinv);

    static bool attr_set = false;
    if (!attr_set) {
        cudaFuncSetAttribute(topp_kernel,
                             cudaFuncAttributeMaxDynamicSharedMemorySize,
                             NN * sizeof(unsigned long long));
        attr_set = true;
    }

    const size_t XB = (size_t)NN * DD * sizeof(float);

    rowsum_kernel<<<NN, 256>>>(S, rinv);
    cudaMemcpyAsync(Xf, X, XB, cudaMemcpyDeviceToDevice);
    cudaMemcpyAsync(Xa, X, XB, cudaMemcpyDeviceToDevice);
    cudaMemsetAsync(Z, 0, XB);

    for (int n = 0; n < 2; n++) {
        // q = (Xa @ W1^T) @ W2^T ; k = Xa @ W3^T
        gemm_kernel<1, 0><<<dim3(1, NN / BM), 256>>>(Xa, W1, t, NN, DA, DD, nullptr, nullptr);
        gemm_kernel<1, 0><<<dim3(1, NN / BM), 256>>>(t,  W2, q, NN, DA, DA, nullptr, nullptr);
        gemm_kernel<1, 0><<<dim3(1, NN / BM), 256>>>(Xa, W3, k, NN, DA, DD, nullptr, nullptr);

        // logits = q @ k^T
        gemm_kernel<1, 0><<<dim3(NN / BN, NN / BM), 256>>>(q, k, L, NN, NN, DA, nullptr, nullptr);

        // softmax + top-p (literal reference semantics) -> A, in place
        topp_kernel<<<NN, 256, NN * sizeof(unsigned long long)>>>(L);

        // Xf2 = rinv * (S @ Xf + Xf)   (== R @ Xf with R = rownorm(S + I))
        gemm_kernel<0, 1><<<dim3(DD / BN, NN / BM), 256>>>(S, Xf, Xf2, NN, DD, NN, Xf, rinv);
        // Xa2 = A @ Xa
        gemm_kernel<0, 0><<<dim3(DD / BN, NN / BM), 256>>>(L, Xa, Xa2, NN, DD, NN, nullptr, nullptr);

        // Z += Xf2 @ U1[n]^T + Xa2 @ U2[n]^T
        gemm_kernel<1, 2><<<dim3(DD / BN, NN / BM), 256>>>(Xf2, U1 + (size_t)n * DD * DD, Z, NN, DD, DD, nullptr, nullptr);
        gemm_kernel<1, 2><<<dim3(DD / BN, NN / BM), 256>>>(Xa2, U2 + (size_t)n * DD * DD, Z, NN, DD, DD, nullptr, nullptr);

        { float* tmp = Xf; Xf = Xf2; Xf2 = tmp; }
        { float* tmp = Xa; Xa = Xa2; Xa2 = tmp; }
    }

    ln_kernel<<<NN, 256>>>(X, Z, lng, lnb, out);
}

// round 12
// speedup vs baseline: 1.5360x; 1.5360x over previous
#include <cuda_runtime.h>
#include <cuda_bf16.h>
#include <math.h>

#define NN 8192
#define DD 256
#define DA 64

// ---------------- scratch (device globals; no allocations allowed) -------------
__device__ float g_L[(size_t)NN * NN];        // logits / A (in place)
__device__ float g_q[NN * DA];
__device__ float g_k[NN * DA];
__device__ float g_t[NN * DA];
__device__ float g_Xf[NN * DD];
__device__ float g_Xf2[NN * DD];
__device__ float g_Xa[NN * DD];
__device__ float g_Xa2[NN * DD];
__device__ float g_Z[NN * DD];
__device__ float g_rinv[NN];

// ---------------- block reductions (256 threads, broadcast result) -------------
__device__ __forceinline__ float blk_sum(float x, float* sm) {
    #pragma unroll
    for (int o = 16; o > 0; o >>= 1) x += __shfl_xor_sync(0xffffffffu, x, o);
    int w = threadIdx.x >> 5;
    __syncthreads();
    if ((threadIdx.x & 31) == 0) sm[w] = x;
    __syncthreads();
    float r = 0.f;
    #pragma unroll
    for (int i = 0; i < 8; i++) r += sm[i];
    return r;
}

__device__ __forceinline__ float blk_max(float x, float* sm) {
    #pragma unroll
    for (int o = 16; o > 0; o >>= 1) x = fmaxf(x, __shfl_xor_sync(0xffffffffu, x, o));
    int w = threadIdx.x >> 5;
    __syncthreads();
    if ((threadIdx.x & 31) == 0) sm[w] = x;
    __syncthreads();
    float r = -INFINITY;
    #pragma unroll
    for (int i = 0; i < 8; i++) r = fmaxf(r, sm[i]);
    return r;
}

__device__ __forceinline__ double blk_sum_d(double x, double* smd) {
    #pragma unroll
    for (int o = 16; o > 0; o >>= 1) x += __shfl_xor_sync(0xffffffffu, x, o);
    int w = threadIdx.x >> 5;
    __syncthreads();
    if ((threadIdx.x & 31) == 0) smd[w] = x;
    __syncthreads();
    double r = 0.0;
    #pragma unroll
    for (int i = 0; i < 8; i++) r += smd[i];
    return r;
}

// ---------------- row sums of S -> rinv = 1/(1 + sum) --------------------------
__global__ void rowsum_kernel(const float* __restrict__ S, float* __restrict__ rinv) {
    __shared__ float sm[8];
    int row = blockIdx.x;
    const float* Sr = S + (size_t)row * NN;
    float s = 0.f;
    for (int j = threadIdx.x; j < NN; j += 256) s += Sr[j];
    s = blk_sum(s, sm);
    if (threadIdx.x == 0) rinv[row] = 1.0f / (s + 1.0f);
}

// ---------------- fp32 SIMT GEMM, double-buffered smem -------------------------
// Per-output accumulation order (strict ascending k, single fp32 accumulator) is
// UNCHANGED vs the validated kernel -- only load scheduling differs, so results
// are bit-identical.
// TRANSB=1: B is [N,K] row-major (NT).  TRANSB=0: B is [K,N] row-major (NN).
// EPI: 0 -> C = acc ; 1 -> C = rscale[row]*(acc + Xadd[row,col]) ; 2 -> C += acc
#define BM 128
#define BN 128
#define BK 16
#define SPAD 4

template<int TRANSB, int EPI>
__global__ void __launch_bounds__(256) gemm_kernel(
    const float* __restrict__ A, const float* __restrict__ B, float* __restrict__ C,
    int M, int N, int K,
    const float* __restrict__ Xadd, const float* __restrict__ rscale)
{
    __shared__ float As[2][BK][BM + SPAD];
    __shared__ float Bs[2][BK][BN + SPAD];

    const int tid = threadIdx.x;
    const int m0 = blockIdx.y * BM;
    const int n0 = blockIdx.x * BN;
    const int tx = tid & 15;
    const int ty = tid >> 4;

    // per-thread load coordinates
    const int ar = (tid >> 2);          // A row within tile (two halves: +0, +64)
    const int ac = (tid & 3) * 4;       // A col (k) within tile
    const int br_t = (tid >> 2);        // TRANSB=1: B n-row within tile
    const int bc_t = (tid & 3) * 4;     // TRANSB=1: B k-col within tile
    const int br_n = (tid >> 5);        // TRANSB=0: B k-row within tile (two: +0,+8)
    const int bc_n = (tid & 31) * 4;    // TRANSB=0: B n-col within tile

    float acc[8][8];
    #pragma unroll
    for (int i = 0; i < 8; i++)
        #pragma unroll
        for (int j = 0; j < 8; j++) acc[i][j] = 0.f;

    const int T = K / BK;

    float4 pa[2], pb[2];

    // prefetch tile 0 into regs
    {
        const int k0 = 0;
        #pragma unroll
        for (int it = 0; it < 2; it++)
            pa[it] = *(const float4*)(A + (size_t)(m0 + ar + it * 64) * K + k0 + ac);
        if (TRANSB) {
            #pragma unroll
            for (int it = 0; it < 2; it++) {
                int r = br_t + it * 64;
                pb[it] = make_float4(0.f, 0.f, 0.f, 0.f);
                if (n0 + r < N)
                    pb[it] = *(const float4*)(B + (size_t)(n0 + r) * K + k0 + bc_t);
            }
        } else {
            #pragma unroll
            for (int it = 0; it < 2; it++) {
                int r = br_n + it * 8;
                pb[it] = make_float4(0.f, 0.f, 0.f, 0.f);
                if (n0 + bc_n < N)
                    pb[it] = *(const float4*)(B + (size_t)(k0 + r) * N + n0 + bc_n);
            }
        }
    }
    // store tile 0 into buffer 0
    {
        #pragma unroll
        for (int it = 0; it < 2; it++) {
            int r = ar + it * 64;
            As[0][ac + 0][r] = pa[it].x; As[0][ac + 1][r] = pa[it].y;
            As[0][ac + 2][r] = pa[it].z; As[0][ac + 3][r] = pa[it].w;
        }
        if (TRANSB) {
            #pragma unroll
            for (int it = 0; it < 2; it++) {
                int r = br_t + it * 64;
                Bs[0][bc_t + 0][r] = pb[it].x; Bs[0][bc_t + 1][r] = pb[it].y;
                Bs[0][bc_t + 2][r] = pb[it].z; Bs[0][bc_t + 3][r] = pb[it].w;
            }
        } else {
            #pragma unroll
            for (int it = 0; it < 2; it++)
                *(float4*)&Bs[0][br_n + it * 8][bc_n] = pb[it];
        }
    }
    __syncthreads();

    for (int t = 0; t < T; t++) {
        const int cur = t & 1;
        const int nxt = cur ^ 1;

        // issue global prefetch for tile t+1 (latency overlaps compute below)
        if (t + 1 < T) {
            const int k0 = (t + 1) * BK;
            #pragma unroll
            for (int it = 0; it < 2; it++)
                pa[it] = *(const float4*)(A + (size_t)(m0 + ar + it * 64) * K + k0 + ac);
            if (TRANSB) {
                #pragma unroll
                for (int it = 0; it < 2; it++) {
                    int r = br_t + it * 64;
                    pb[it] = make_float4(0.f, 0.f, 0.f, 0.f);
                    if (n0 + r < N)
                        pb[it] = *(const float4*)(B + (size_t)(n0 + r) * K + k0 + bc_t);
                }
            } else {
                #pragma unroll
                for (int it = 0; it < 2; it++) {
                    int r = br_n + it * 8;
                    pb[it] = make_float4(0.f, 0.f, 0.f, 0.f);
                    if (n0 + bc_n < N)
                        pb[it] = *(const float4*)(B + (size_t)(k0 + r) * N + n0 + bc_n);
                }
            }
        }

        // compute on current buffer (ascending k -- identical accumulation order)
        #pragma unroll
        for (int k = 0; k < BK; k++) {
            float a[8], b[8];
            *(float4*)&a[0] = *(const float4*)&As[cur][k][ty * 8];
            *(float4*)&a[4] = *(const float4*)&As[cur][k][ty * 8 + 4];
            *(float4*)&b[0] = *(const float4*)&Bs[cur][k][tx * 8];
            *(float4*)&b[4] = *(const float4*)&Bs[cur][k][tx * 8 + 4];
            #pragma unroll
            for (int i = 0; i < 8; i++)
                #pragma unroll
                for (int j = 0; j < 8; j++)
                    acc[i][j] = fmaf(a[i], b[j], acc[i][j]);
        }

        // store prefetched tile into the other buffer
        if (t + 1 < T) {
            #pragma unroll
            for (int it = 0; it < 2; it++) {
                int r = ar + it * 64;
                As[nxt][ac + 0][r] = pa[it].x; As[nxt][ac + 1][r] = pa[it].y;
                As[nxt][ac + 2][r] = pa[it].z; As[nxt][ac + 3][r] = pa[it].w;
            }
            if (TRANSB) {
                #pragma unroll
                for (int it = 0; it < 2; it++) {
                    int r = br_t + it * 64;
                    Bs[nxt][bc_t + 0][r] = pb[it].x; Bs[nxt][bc_t + 1][r] = pb[it].y;
                    Bs[nxt][bc_t + 2][r] = pb[it].z; Bs[nxt][bc_t + 3][r] = pb[it].w;
                }
            } else {
                #pragma unroll
                for (int it = 0; it < 2; it++)
                    *(float4*)&Bs[nxt][br_n + it * 8][bc_n] = pb[it];
            }
        }
        __syncthreads();
    }

    #pragma unroll
    for (int i = 0; i < 8; i++) {
        int row = m0 + ty * 8 + i;
        float rs = (EPI == 1) ? rscale[row] : 0.f;
        #pragma unroll
        for (int jj = 0; jj < 2; jj++) {
            int col = n0 + tx * 8 + jj * 4;
            if (col < N) {
                size_t idx = (size_t)row * N + col;
                float4 v;
                v.x = acc[i][jj * 4 + 0]; v.y = acc[i][jj * 4 + 1];
                v.z = acc[i][jj * 4 + 2]; v.w = acc[i][jj * 4 + 3];
                if (EPI == 1) {
                    float4 ad = *(const float4*)(Xadd + idx);
                    v.x = rs * (v.x + ad.x); v.y = rs * (v.y + ad.y);
                    v.z = rs * (v.z + ad.z); v.w = rs * (v.w + ad.w);
                } else if (EPI == 2) {
                    float4 cv = *(const float4*)(C + idx);
                    v.x += cv.x; v.y += cv.y; v.z += cv.z; v.w += cv.w;
                }
                *(float4*)(C + idx) = v;
            }
        }
    }
}

// ---------------- top-p: literal reference semantics, candidate-pruned sort ----
// Identical math to the validated kernel (double exp, fp32 div probs, u64 keys,
// descending bitonic, fp32 cumsum walk, double kept-mass, scatter), except only
// a provable SUPERSET of the kept prefix is sorted: candidates = {p >= thr} with
// candidate mass >= 0.92 (2% slack >> fp32 walk drift), found by a cheap fp32
// binary search. The kept prefix of the global sort is contained in any top-
// prefix of mass >= 0.9 + drift, so the walk over sorted candidates produces the
// bitwise-identical kept set.
__global__ void __launch_bounds__(256) topp_kernel(float* __restrict__ L) {
    extern __shared__ unsigned long long key[];   // capacity 8192 (64KB)
    __shared__ float sm[8];
    __shared__ double smd[8];
    __shared__ int s_cnt;
    __shared__ int s_jstop;
    __shared__ float s_inv;

    const int row = blockIdx.x;
    const int tid = threadIdx.x;
    float* Lr = L + (size_t)row * NN;

    float v[32];
    #pragma unroll
    for (int i = 0; i < 32; i++) v[i] = Lr[i * 256 + tid];

    float m = -INFINITY;
    #pragma unroll
    for (int i = 0; i < 32; i++) m = fmaxf(m, v[i]);
    m = blk_max(m, sm);

    // e-values with correctly-rounded exp (double-internal) -- unchanged
    double zloc = 0.0;
    #pragma unroll
    for (int i = 0; i < 32; i++) {
        v[i] = (float)exp((double)(v[i] - m));
        zloc += (double)v[i];
    }
    double Zd = blk_sum_d(zloc, smd);
    const float Zf = (float)Zd;

    // probs (fp32 division) -- unchanged values
    float ploc = 0.f;
    #pragma unroll
    for (int i = 0; i < 32; i++) {
        v[i] = __fdiv_rn(v[i], Zf);
        ploc += v[i];
    }
    const float Ptot = blk_sum(ploc, sm);
    const float target = 0.92f * Ptot;   // 2% slack over the 0.9 walk target

    // binary search (fp32 sums are plenty against the 2% slack):
    // largest u with  sum{p > float(u)} >= target
    unsigned lo = 0u, hi = 0x3F800000u;
    while (lo < hi) {
        unsigned mid = (lo + hi + 1u) >> 1;
        float t = __uint_as_float(mid);
        float s = 0.f;
        #pragma unroll
        for (int i = 0; i < 32; i++) s += (v[i] > t) ? v[i] : 0.f;
        s = blk_sum(s, sm);
        if (s >= target) lo = mid; else hi = mid - 1u;
    }
    const float thr = __uint_as_float(lo);

    // compact candidates {p >= thr} into key[]; sort canonicalizes order later
    if (tid == 0) s_cnt = 0;
    __syncthreads();
    #pragma unroll
    for (int i = 0; i < 32; i++) {
        if (v[i] >= thr) {
            int idx = i * 256 + tid;
            int slot = atomicAdd(&s_cnt, 1);
            key[slot] = ((unsigned long long)__float_as_uint(v[i]) << 32)
                      | (unsigned long long)(0xFFFFFFFFu - (unsigned)idx);
        }
    }
    __syncthreads();
    const int cnt = s_cnt;

    int C2 = 1;
    while (C2 < cnt) C2 <<= 1;
    for (int i = cnt + tid; i < C2; i += 256) key[i] = 0ull;  // pad: sorts last
    __syncthreads();

    // bitonic sort of C2 elements, DESCENDING (same comparator as validated)
    for (int k2 = 2; k2 <= C2; k2 <<= 1) {
        for (int j = k2 >> 1; j > 0; j >>= 1) {
            for (int base = 0; base < C2; base += 256) {
                int i = base + tid;
                if (i < C2) {
                    int ij = i ^ j;
                    if (ij > i) {
                        unsigned long long a = key[i];
                        unsigned long long b = key[ij];
                        bool descBlock = ((i & k2) == 0);
                        if (descBlock ? (a < b) : (a > b)) {
                            key[i] = b;
                            key[ij] = a;
                        }
                    }
                }
            }
            __syncthreads();
        }
    }

    // sequential fp32 cumsum walk (bitwise-faithful), early exit
    if (tid == 0) {
        float cs = 0.f;
        int j = 0;
        for (; j < cnt; j++) {
            float p = __uint_as_float((unsigned)(key[j] >> 32));
            cs = __fadd_rn(cs, p);
            float excl = __fsub_rn(cs, p);
            if (!(excl < 0.9f)) break;     // first dropped position
        }
        s_jstop = j;                        // kept = sorted positions [0, j)
    }
    __syncthreads();
    const int jstop = s_jstop;

    // kept mass (double) -> inv  -- unchanged
    {
        double ks = 0.0;
        for (int p0 = tid; p0 < jstop; p0 += 256)
            ks += (double)__uint_as_float((unsigned)(key[p0] >> 32));
        double ksd = blk_sum_d(ks, smd);
        if (tid == 0) s_inv = (float)(1.0 / fmax(ksd, 1e-12));
    }
    __syncthreads();
    const float inv = s_inv;

    // zero the row, then scatter kept entries -- unchanged
    #pragma unroll
    for (int i = 0; i < 32; i++) Lr[i * 256 + tid] = 0.f;
    __syncthreads();
    for (int p0 = tid; p0 < jstop; p0 += 256) {
        unsigned long long kk = key[p0];
        unsigned orig = 0xFFFFFFFFu - (unsigned)(kk & 0xFFFFFFFFull);
        float p = __uint_as_float((unsigned)(kk >> 32));
        Lr[orig] = p * inv;
    }
}

// ---------------- final residual + layernorm -----------------------------------
__global__ void __launch_bounds__(256) ln_kernel(
    const float* __restrict__ X, const float* __restrict__ Z,
    const float* __restrict__ g, const float* __restrict__ b,
    float* __restrict__ out)
{
    __shared__ float sm[8];
    int row = blockIdx.x;
    int c = threadIdx.x;
    size_t idx = (size_t)row * DD + c;
    float h = X[idx] + Z[idx];
    float s1 = blk_sum(h, sm);
    float mu = s1 * (1.0f / DD);
    float d = h - mu;
    float s2 = blk_sum(d * d, sm);
    float var = s2 * (1.0f / DD);
    out[idx] = d * rsqrtf(var + 1e-5f) * g[c] + b[c];
}

// ---------------- host orchestration -------------------------------------------
extern "C" void kernel_launch(void* const* d_in, const int* in_sizes, int n_in,
                              void* d_out, int out_size) {
    const float* X   = (const float*)d_in[0];
    const float* S   = (const float*)d_in[1];
    const float* W1  = (const float*)d_in[2];
    const float* W2  = (const float*)d_in[3];
    const float* W3  = (const float*)d_in[4];
    const float* U1  = (const float*)d_in[5];
    const float* U2  = (const float*)d_in[6];
    const float* lng = (const float*)d_in[7];
    const float* lnb = (const float*)d_in[8];
    float* out = (float*)d_out;

    float *L, *q, *k, *t, *Xf, *Xf2, *Xa, *Xa2, *Z, *rinv;
    cudaGetSymbolAddress((void**)&L,    g_L);
    cudaGetSymbolAddress((void**)&q,    g_q);
    cudaGetSymbolAddress((void**)&k,    g_k);
    cudaGetSymbolAddress((void**)&t,    g_t);
    cudaGetSymbolAddress((void**)&Xf,   g_Xf);
    cudaGetSymbolAddress((void**)&Xf2,  g_Xf2);
    cudaGetSymbolAddress((void**)&Xa,   g_Xa);
    cudaGetSymbolAddress((void**)&Xa2,  g_Xa2);
    cudaGetSymbolAddress((void**)&Z,    g_Z);
    cudaGetSymbolAddress((void**)&rinv, g_rinv);

    static bool attr_set = false;
    if (!attr_set) {
        cudaFuncSetAttribute(topp_kernel,
                             cudaFuncAttributeMaxDynamicSharedMemorySize,
                             NN * sizeof(unsigned long long));
        attr_set = true;
    }

    const size_t XB = (size_t)NN * DD * sizeof(float);

    rowsum_kernel<<<NN, 256>>>(S, rinv);
    cudaMemcpyAsync(Xf, X, XB, cudaMemcpyDeviceToDevice);
    cudaMemcpyAsync(Xa, X, XB, cudaMemcpyDeviceToDevice);
    cudaMemsetAsync(Z, 0, XB);

    for (int n = 0; n < 2; n++) {
        // q = (Xa @ W1^T) @ W2^T ; k = Xa @ W3^T
        gemm_kernel<1, 0><<<dim3(1, NN / BM), 256>>>(Xa, W1, t, NN, DA, DD, nullptr, nullptr);
        gemm_kernel<1, 0><<<dim3(1, NN / BM), 256>>>(t,  W2, q, NN, DA, DA, nullptr, nullptr);
        gemm_kernel<1, 0><<<dim3(1, NN / BM), 256>>>(Xa, W3, k, NN, DA, DD, nullptr, nullptr);

        // logits = q @ k^T
        gemm_kernel<1, 0><<<dim3(NN / BN, NN / BM), 256>>>(q, k, L, NN, NN, DA, nullptr, nullptr);

        // softmax + top-p (literal reference semantics, pruned sort) -> A
        topp_kernel<<<NN, 256, NN * sizeof(unsigned long long)>>>(L);

        // Xf2 = rinv * (S @ Xf + Xf)   (== R @ Xf with R = rownorm(S + I))
        gemm_kernel<0, 1><<<dim3(DD / BN, NN / BM), 256>>>(S, Xf, Xf2, NN, DD, NN, Xf, rinv);
        // Xa2 = A @ Xa
        gemm_kernel<0, 0><<<dim3(DD / BN, NN / BM), 256>>>(L, Xa, Xa2, NN, DD, NN, nullptr, nullptr);

        // Z += Xf2 @ U1[n]^T + Xa2 @ U2[n]^T
        gemm_kernel<1, 2><<<dim3(DD / BN, NN / BM), 256>>>(Xf2, U1 + (size_t)n * DD * DD, Z, NN, DD, DD, nullptr, nullptr);
        gemm_kernel<1, 2><<<dim3(DD / BN, NN / BM), 256>>>(Xa2, U2 + (size_t)n * DD * DD, Z, NN, DD, DD, nullptr, nullptr);

        { float* tmp = Xf; Xf = Xf2; Xf2 = tmp; }
        { float* tmp = Xa; Xa = Xa2; Xa2 = tmp; }
    }

    ln_kernel<<<NN, 256>>>(X, Z, lng, lnb, out);
}

// round 15
// speedup vs baseline: 1.8992x; 1.2365x over previous
#include <cuda_runtime.h>
#include <cuda_bf16.h>
#include <math.h>

#define NN 8192
#define DD 256
#define DA 64

// ---------------- scratch (device globals; no allocations allowed) -------------
__device__ float g_L[(size_t)NN * NN];        // logits -> CSR values (in place)
__device__ int   g_Aidx[(size_t)NN * NN];     // CSR column indices
__device__ int   g_Annz[NN];                  // CSR nnz per row
__device__ float g_q[NN * DA];
__device__ float g_k[NN * DA];
__device__ float g_t[NN * DA];
__device__ float g_Xf[NN * DD];
__device__ float g_Xf2[NN * DD];
__device__ float g_Xa[NN * DD];
__device__ float g_Xa2[NN * DD];
__device__ float g_Z[NN * DD];
__device__ float g_rinv[NN];

// ---------------- block reductions (256 threads, broadcast result) -------------
__device__ __forceinline__ float blk_sum(float x, float* sm) {
    #pragma unroll
    for (int o = 16; o > 0; o >>= 1) x += __shfl_xor_sync(0xffffffffu, x, o);
    int w = threadIdx.x >> 5;
    __syncthreads();
    if ((threadIdx.x & 31) == 0) sm[w] = x;
    __syncthreads();
    float r = 0.f;
    #pragma unroll
    for (int i = 0; i < 8; i++) r += sm[i];
    return r;
}

__device__ __forceinline__ float blk_max(float x, float* sm) {
    #pragma unroll
    for (int o = 16; o > 0; o >>= 1) x = fmaxf(x, __shfl_xor_sync(0xffffffffu, x, o));
    int w = threadIdx.x >> 5;
    __syncthreads();
    if ((threadIdx.x & 31) == 0) sm[w] = x;
    __syncthreads();
    float r = -INFINITY;
    #pragma unroll
    for (int i = 0; i < 8; i++) r = fmaxf(r, sm[i]);
    return r;
}

__device__ __forceinline__ double blk_sum_d(double x, double* smd) {
    #pragma unroll
    for (int o = 16; o > 0; o >>= 1) x += __shfl_xor_sync(0xffffffffu, x, o);
    int w = threadIdx.x >> 5;
    __syncthreads();
    if ((threadIdx.x & 31) == 0) smd[w] = x;
    __syncthreads();
    double r = 0.0;
    #pragma unroll
    for (int i = 0; i < 8; i++) r += smd[i];
    return r;
}

// ---------------- row sums of S -> rinv = 1/(1 + sum) --------------------------
__global__ void rowsum_kernel(const float* __restrict__ S, float* __restrict__ rinv) {
    __shared__ float sm[8];
    int row = blockIdx.x;
    const float* Sr = S + (size_t)row * NN;
    float s = 0.f;
    for (int j = threadIdx.x; j < NN; j += 256) s += Sr[j];
    s = blk_sum(s, sm);
    if (threadIdx.x == 0) rinv[row] = 1.0f / (s + 1.0f);
}

// ---------------- fp32 SIMT GEMM, double-buffered smem, 2 CTA/SM ---------------
// Per-output accumulation order (strict ascending k, single fp32 accumulator) is
// UNCHANGED -- only load scheduling/occupancy differ, so results are bit-identical.
// TRANSB=1: B is [N,K] row-major (NT).  TRANSB=0: B is [K,N] row-major (NN).
// EPI: 0 -> C = acc ; 1 -> C = rscale[row]*(acc + Xadd[row,col]) ; 2 -> C += acc
#define BM 128
#define BN 128
#define BK 16
#define SPAD 4

template<int TRANSB, int EPI>
__global__ void __launch_bounds__(256, 2) gemm_kernel(
    const float* __restrict__ A, const float* __restrict__ B, float* __restrict__ C,
    int M, int N, int K,
    const float* __restrict__ Xadd, const float* __restrict__ rscale)
{
    __shared__ float As[2][BK][BM + SPAD];
    __shared__ float Bs[2][BK][BN + SPAD];

    const int tid = threadIdx.x;
    const int m0 = blockIdx.y * BM;
    const int n0 = blockIdx.x * BN;
    const int tx = tid & 15;
    const int ty = tid >> 4;

    const int ar = (tid >> 2);          // A row within tile (two halves: +0, +64)
    const int ac = (tid & 3) * 4;       // A col (k) within tile
    const int br_t = (tid >> 2);        // TRANSB=1: B n-row within tile
    const int bc_t = (tid & 3) * 4;     // TRANSB=1: B k-col within tile
    const int br_n = (tid >> 5);        // TRANSB=0: B k-row within tile (+0,+8)
    const int bc_n = (tid & 31) * 4;    // TRANSB=0: B n-col within tile

    float acc[8][8];
    #pragma unroll
    for (int i = 0; i < 8; i++)
        #pragma unroll
        for (int j = 0; j < 8; j++) acc[i][j] = 0.f;

    const int T = K / BK;
    float4 pa[2], pb[2];

    {
        const int k0 = 0;
        #pragma unroll
        for (int it = 0; it < 2; it++)
            pa[it] = *(const float4*)(A + (size_t)(m0 + ar + it * 64) * K + k0 + ac);
        if (TRANSB) {
            #pragma unroll
            for (int it = 0; it < 2; it++) {
                int r = br_t + it * 64;
                pb[it] = make_float4(0.f, 0.f, 0.f, 0.f);
                if (n0 + r < N)
                    pb[it] = *(const float4*)(B + (size_t)(n0 + r) * K + k0 + bc_t);
            }
        } else {
            #pragma unroll
            for (int it = 0; it < 2; it++) {
                int r = br_n + it * 8;
                pb[it] = make_float4(0.f, 0.f, 0.f, 0.f);
                if (n0 + bc_n < N)
                    pb[it] = *(const float4*)(B + (size_t)(k0 + r) * N + n0 + bc_n);
            }
        }
    }
    {
        #pragma unroll
        for (int it = 0; it < 2; it++) {
            int r = ar + it * 64;
            As[0][ac + 0][r] = pa[it].x; As[0][ac + 1][r] = pa[it].y;
            As[0][ac + 2][r] = pa[it].z; As[0][ac + 3][r] = pa[it].w;
        }
        if (TRANSB) {
            #pragma unroll
            for (int it = 0; it < 2; it++) {
                int r = br_t + it * 64;
                Bs[0][bc_t + 0][r] = pb[it].x; Bs[0][bc_t + 1][r] = pb[it].y;
                Bs[0][bc_t + 2][r] = pb[it].z; Bs[0][bc_t + 3][r] = pb[it].w;
            }
        } else {
            #pragma unroll
            for (int it = 0; it < 2; it++)
                *(float4*)&Bs[0][br_n + it * 8][bc_n] = pb[it];
        }
    }
    __syncthreads();

    for (int t = 0; t < T; t++) {
        const int cur = t & 1;
        const int nxt = cur ^ 1;

        if (t + 1 < T) {
            const int k0 = (t + 1) * BK;
            #pragma unroll
            for (int it = 0; it < 2; it++)
                pa[it] = *(const float4*)(A + (size_t)(m0 + ar + it * 64) * K + k0 + ac);
            if (TRANSB) {
                #pragma unroll
                for (int it = 0; it < 2; it++) {
                    int r = br_t + it * 64;
                    pb[it] = make_float4(0.f, 0.f, 0.f, 0.f);
                    if (n0 + r < N)
                        pb[it] = *(const float4*)(B + (size_t)(n0 + r) * K + k0 + bc_t);
                }
            } else {
                #pragma unroll
                for (int it = 0; it < 2; it++) {
                    int r = br_n + it * 8;
                    pb[it] = make_float4(0.f, 0.f, 0.f, 0.f);
                    if (n0 + bc_n < N)
                        pb[it] = *(const float4*)(B + (size_t)(k0 + r) * N + n0 + bc_n);
                }
            }
        }

        #pragma unroll
        for (int k = 0; k < BK; k++) {
            float a[8], b[8];
            *(float4*)&a[0] = *(const float4*)&As[cur][k][ty * 8];
            *(float4*)&a[4] = *(const float4*)&As[cur][k][ty * 8 + 4];
            *(float4*)&b[0] = *(const float4*)&Bs[cur][k][tx * 8];
            *(float4*)&b[4] = *(const float4*)&Bs[cur][k][tx * 8 + 4];
            #pragma unroll
            for (int i = 0; i < 8; i++)
                #pragma unroll
                for (int j = 0; j < 8; j++)
                    acc[i][j] = fmaf(a[i], b[j], acc[i][j]);
        }

        if (t + 1 < T) {
            #pragma unroll
            for (int it = 0; it < 2; it++) {
                int r = ar + it * 64;
                As[nxt][ac + 0][r] = pa[it].x; As[nxt][ac + 1][r] = pa[it].y;
                As[nxt][ac + 2][r] = pa[it].z; As[nxt][ac + 3][r] = pa[it].w;
            }
            if (TRANSB) {
                #pragma unroll
                for (int it = 0; it < 2; it++) {
                    int r = br_t + it * 64;
                    Bs[nxt][bc_t + 0][r] = pb[it].x; Bs[nxt][bc_t + 1][r] = pb[it].y;
                    Bs[nxt][bc_t + 2][r] = pb[it].z; Bs[nxt][bc_t + 3][r] = pb[it].w;
                }
            } else {
                #pragma unroll
                for (int it = 0; it < 2; it++)
                    *(float4*)&Bs[nxt][br_n + it * 8][bc_n] = pb[it];
            }
        }
        __syncthreads();
    }

    #pragma unroll
    for (int i = 0; i < 8; i++) {
        int row = m0 + ty * 8 + i;
        float rs = (EPI == 1) ? rscale[row] : 0.f;
        #pragma unroll
        for (int jj = 0; jj < 2; jj++) {
            int col = n0 + tx * 8 + jj * 4;
            if (col < N) {
                size_t idx = (size_t)row * N + col;
                float4 v;
                v.x = acc[i][jj * 4 + 0]; v.y = acc[i][jj * 4 + 1];
                v.z = acc[i][jj * 4 + 2]; v.w = acc[i][jj * 4 + 3];
                if (EPI == 1) {
                    float4 ad = *(const float4*)(Xadd + idx);
                    v.x = rs * (v.x + ad.x); v.y = rs * (v.y + ad.y);
                    v.z = rs * (v.z + ad.z); v.w = rs * (v.w + ad.w);
                } else if (EPI == 2) {
                    float4 cv = *(const float4*)(C + idx);
                    v.x += cv.x; v.y += cv.y; v.z += cv.z; v.w += cv.w;
                }
                *(float4*)(C + idx) = v;
            }
        }
    }
}

// ---------------- top-p -> CSR (literal reference semantics) -------------------
// Same validated math (double exp, fp32 div probs, u64 keys, descending bitonic
// over a provable candidate superset, fp32 cumsum walk, double kept-mass).
// NEW: instead of scattering a dense A row, emit CSR sorted ASCENDING by column
// index (second small bitonic). Values = p * inv (same op). Downstream SpMM in
// ascending-index order is bitwise identical to the dense ascending-k GEMM,
// because fmaf(0, x, acc) == acc exactly.
__global__ void __launch_bounds__(256) topp_kernel(float* __restrict__ L,
                                                   int* __restrict__ Aidx,
                                                   int* __restrict__ Annz) {
    extern __shared__ unsigned long long key[];   // capacity 8192 (64KB)
    __shared__ float sm[8];
    __shared__ double smd[8];
    __shared__ int s_cnt;
    __shared__ int s_jstop;
    __shared__ float s_inv;

    const int row = blockIdx.x;
    const int tid = threadIdx.x;
    float* Lr = L + (size_t)row * NN;

    float v[32];
    #pragma unroll
    for (int i = 0; i < 32; i++) v[i] = Lr[i * 256 + tid];

    float m = -INFINITY;
    #pragma unroll
    for (int i = 0; i < 32; i++) m = fmaxf(m, v[i]);
    m = blk_max(m, sm);

    double zloc = 0.0;
    #pragma unroll
    for (int i = 0; i < 32; i++) {
        v[i] = (float)exp((double)(v[i] - m));
        zloc += (double)v[i];
    }
    double Zd = blk_sum_d(zloc, smd);
    const float Zf = (float)Zd;

    float ploc = 0.f;
    #pragma unroll
    for (int i = 0; i < 32; i++) {
        v[i] = __fdiv_rn(v[i], Zf);
        ploc += v[i];
    }
    const float Ptot = blk_sum(ploc, sm);
    const float target = 0.92f * Ptot;   // 2% slack over the 0.9 walk target

    // largest u with  sum{p > float(u)} >= target  (superset guarantee)
    unsigned lo = 0u, hi = 0x3F800000u;
    while (lo < hi) {
        unsigned mid = (lo + hi + 1u) >> 1;
        float t = __uint_as_float(mid);
        float s = 0.f;
        #pragma unroll
        for (int i = 0; i < 32; i++) s += (v[i] > t) ? v[i] : 0.f;
        s = blk_sum(s, sm);
        if (s >= target) lo = mid; else hi = mid - 1u;
    }
    const float thr = __uint_as_float(lo);

    if (tid == 0) s_cnt = 0;
    __syncthreads();
    #pragma unroll
    for (int i = 0; i < 32; i++) {
        if (v[i] >= thr) {
            int idx = i * 256 + tid;
            int slot = atomicAdd(&s_cnt, 1);
            key[slot] = ((unsigned long long)__float_as_uint(v[i]) << 32)
                      | (unsigned long long)(0xFFFFFFFFu - (unsigned)idx);
        }
    }
    __syncthreads();
    const int cnt = s_cnt;

    int C2 = 1;
    while (C2 < cnt) C2 <<= 1;
    for (int i = cnt + tid; i < C2; i += 256) key[i] = 0ull;  // pad: sorts last
    __syncthreads();

    // bitonic sort, DESCENDING by u64 key (prob-major, ascending-index ties)
    for (int k2 = 2; k2 <= C2; k2 <<= 1) {
        for (int j = k2 >> 1; j > 0; j >>= 1) {
            for (int base = 0; base < C2; base += 256) {
                int i = base + tid;
                if (i < C2) {
                    int ij = i ^ j;
                    if (ij > i) {
                        unsigned long long a = key[i];
                        unsigned long long b = key[ij];
                        bool descBlock = ((i & k2) == 0);
                        if (descBlock ? (a < b) : (a > b)) {
                            key[i] = b;
                            key[ij] = a;
                        }
                    }
                }
            }
            __syncthreads();
        }
    }

    // sequential fp32 cumsum walk (bitwise-faithful), early exit
    if (tid == 0) {
        float cs = 0.f;
        int j = 0;
        for (; j < cnt; j++) {
            float p = __uint_as_float((unsigned)(key[j] >> 32));
            cs = __fadd_rn(cs, p);
            float excl = __fsub_rn(cs, p);
            if (!(excl < 0.9f)) break;
        }
        s_jstop = j;                        // kept = sorted positions [0, j)
    }
    __syncthreads();
    const int jstop = s_jstop;

    // kept mass (double) -> inv
    {
        double ks = 0.0;
        for (int p0 = tid; p0 < jstop; p0 += 256)
            ks += (double)__uint_as_float((unsigned)(key[p0] >> 32));
        double ksd = blk_sum_d(ks, smd);
        if (tid == 0) s_inv = (float)(1.0 / fmax(ksd, 1e-12));
    }
    __syncthreads();
    const float inv = s_inv;

    // rekey kept entries as [idx | pbits] for ascending-index sort
    for (int p0 = tid; p0 < jstop; p0 += 256) {
        unsigned long long kk = key[p0];
        unsigned orig = 0xFFFFFFFFu - (unsigned)(kk & 0xFFFFFFFFull);
        unsigned pbits = (unsigned)(kk >> 32);
        key[p0] = ((unsigned long long)orig << 32) | (unsigned long long)pbits;
    }
    __syncthreads();

    int K2 = 1;
    while (K2 < jstop) K2 <<= 1;
    if (K2 < 2) K2 = 2;
    for (int i = jstop + tid; i < K2; i += 256) key[i] = 0xFFFFFFFFFFFFFFFFull;
    __syncthreads();

    // bitonic sort ASCENDING by index
    for (int k2 = 2; k2 <= K2; k2 <<= 1) {
        for (int j = k2 >> 1; j > 0; j >>= 1) {
            for (int base = 0; base < K2; base += 256) {
                int i = base + tid;
                if (i < K2) {
                    int ij = i ^ j;
                    if (ij > i) {
                        unsigned long long a = key[i];
                        unsigned long long b = key[ij];
                        bool ascBlock = ((i & k2) == 0);
                        if (ascBlock ? (a > b) : (a < b)) {
                            key[i] = b;
                            key[ij] = a;
                        }
                    }
                }
            }
            __syncthreads();
        }
    }

    // emit CSR: columns ascending, values = p * inv (same op as validated)
    int* Ar = Aidx + (size_t)row * NN;
    for (int p0 = tid; p0 < jstop; p0 += 256) {
        unsigned long long kk = key[p0];
        Ar[p0] = (int)(kk >> 32);
        Lr[p0] = __uint_as_float((unsigned)(kk & 0xFFFFFFFFull)) * inv;
    }
    if (tid == 0) Annz[row] = jstop;
}

// ---------------- sparse A @ Xa  (bitwise == dense ascending-k GEMM) -----------
// One block per row; thread c owns output column c. Single fp32 accumulator,
// ascending column index -- skipped terms are exact zeros in the dense version.
__global__ void __launch_bounds__(256) spmm_kernel(
    const float* __restrict__ Aval, const int* __restrict__ Aidx,
    const int* __restrict__ Annz,
    const float* __restrict__ Xa, float* __restrict__ Xa2)
{
    const int row = blockIdx.x;
    const int c = threadIdx.x;
    const float* val = Aval + (size_t)row * NN;
    const int* col = Aidx + (size_t)row * NN;
    const int nnz = Annz[row];

    float acc = 0.f;
    int j = 0;
    for (; j + 4 <= nnz; j += 4) {
        float v0 = val[j + 0]; int c0 = col[j + 0];
        float v1 = val[j + 1]; int c1 = col[j + 1];
        float v2 = val[j + 2]; int c2 = col[j + 2];
        float v3 = val[j + 3]; int c3 = col[j + 3];
        acc = fmaf(v0, Xa[(size_t)c0 * DD + c], acc);
        acc = fmaf(v1, Xa[(size_t)c1 * DD + c], acc);
        acc = fmaf(v2, Xa[(size_t)c2 * DD + c], acc);
        acc = fmaf(v3, Xa[(size_t)c3 * DD + c], acc);
    }
    for (; j < nnz; j++)
        acc = fmaf(val[j], Xa[(size_t)col[j] * DD + c], acc);

    Xa2[(size_t)row * DD + c] = acc;
}

// ---------------- final residual + layernorm -----------------------------------
__global__ void __launch_bounds__(256) ln_kernel(
    const float* __restrict__ X, const float* __restrict__ Z,
    const float* __restrict__ g, const float* __restrict__ b,
    float* __restrict__ out)
{
    __shared__ float sm[8];
    int row = blockIdx.x;
    int c = threadIdx.x;
    size_t idx = (size_t)row * DD + c;
    float h = X[idx] + Z[idx];
    float s1 = blk_sum(h, sm);
    float mu = s1 * (1.0f / DD);
    float d = h - mu;
    float s2 = blk_sum(d * d, sm);
    float var = s2 * (1.0f / DD);
    out[idx] = d * rsqrtf(var + 1e-5f) * g[c] + b[c];
}

// ---------------- host orchestration -------------------------------------------
extern "C" void kernel_launch(void* const* d_in, const int* in_sizes, int n_in,
                              void* d_out, int out_size) {
    const float* X   = (const float*)d_in[0];
    const float* S   = (const float*)d_in[1];
    const float* W1  = (const float*)d_in[2];
    const float* W2  = (const float*)d_in[3];
    const float* W3  = (const float*)d_in[4];
    const float* U1  = (const float*)d_in[5];
    const float* U2  = (const float*)d_in[6];
    const float* lng = (const float*)d_in[7];
    const float* lnb = (const float*)d_in[8];
    float* out = (float*)d_out;

    float *L, *q, *k, *t, *Xf, *Xf2, *Xa, *Xa2, *Z, *rinv;
    int *Aidx, *Annz;
    cudaGetSymbolAddress((void**)&L,    g_L);
    cudaGetSymbolAddress((void**)&Aidx, g_Aidx);
    cudaGetSymbolAddress((void**)&Annz, g_Annz);
    cudaGetSymbolAddress((void**)&q,    g_q);
    cudaGetSymbolAddress((void**)&k,    g_k);
    cudaGetSymbolAddress((void**)&t,    g_t);
    cudaGetSymbolAddress((void**)&Xf,   g_Xf);
    cudaGetSymbolAddress((void**)&Xf2,  g_Xf2);
    cudaGetSymbolAddress((void**)&Xa,   g_Xa);
    cudaGetSymbolAddress((void**)&Xa2,  g_Xa2);
    cudaGetSymbolAddress((void**)&Z,    g_Z);
    cudaGetSymbolAddress((void**)&rinv, g_rinv);

    static bool attr_set = false;
    if (!attr_set) {
        cudaFuncSetAttribute(topp_kernel,
                             cudaFuncAttributeMaxDynamicSharedMemorySize,
                             NN * sizeof(unsigned long long));
        attr_set = true;
    }

    const size_t XB = (size_t)NN * DD * sizeof(float);

    rowsum_kernel<<<NN, 256>>>(S, rinv);
    cudaMemcpyAsync(Xf, X, XB, cudaMemcpyDeviceToDevice);
    cudaMemcpyAsync(Xa, X, XB, cudaMemcpyDeviceToDevice);
    cudaMemsetAsync(Z, 0, XB);

    for (int n = 0; n < 2; n++) {
        // q = (Xa @ W1^T) @ W2^T ; k = Xa @ W3^T
        gemm_kernel<1, 0><<<dim3(1, NN / BM), 256>>>(Xa, W1, t, NN, DA, DD, nullptr, nullptr);
        gemm_kernel<1, 0><<<dim3(1, NN / BM), 256>>>(t,  W2, q, NN, DA, DA, nullptr, nullptr);
        gemm_kernel<1, 0><<<dim3(1, NN / BM), 256>>>(Xa, W3, k, NN, DA, DD, nullptr, nullptr);

        // logits = q @ k^T
        gemm_kernel<1, 0><<<dim3(NN / BN, NN / BM), 256>>>(q, k, L, NN, NN, DA, nullptr, nullptr);

        // softmax + top-p (literal reference semantics) -> CSR(A)
        topp_kernel<<<NN, 256, NN * sizeof(unsigned long long)>>>(L, Aidx, Annz);

        // Xa2 = A @ Xa  (sparse; bitwise == dense ascending-k GEMM)
        spmm_kernel<<<NN, 256>>>(L, Aidx, Annz, Xa, Xa2);

        // Xf2 = rinv * (S @ Xf + Xf)   (== R @ Xf with R = rownorm(S + I))
        gemm_kernel<0, 1><<<dim3(DD / BN, NN / BM), 256>>>(S, Xf, Xf2, NN, DD, NN, Xf, rinv);

        // Z += Xf2 @ U1[n]^T + Xa2 @ U2[n]^T
        gemm_kernel<1, 2><<<dim3(DD / BN, NN / BM), 256>>>(Xf2, U1 + (size_t)n * DD * DD, Z, NN, DD, DD, nullptr, nullptr);
        gemm_kernel<1, 2><<<dim3(DD / BN, NN / BM), 256>>>(Xa2, U2 + (size_t)n * DD * DD, Z, NN, DD, DD, nullptr, nullptr);

        { float* tmp = Xf; Xf = Xf2; Xf2 = tmp; }
        { float* tmp = Xa; Xa = Xa2; Xa2 = tmp; }
    }

    ln_kernel<<<NN, 256>>>(X, Z, lng, lnb, out);
}

// round 17
// speedup vs baseline: 4.0750x; 2.1456x over previous
#include <cuda_runtime.h>
#include <cuda_bf16.h>
#include <math.h>

#define NN 8192
#define DD 256
#define DA 64
#define SK 4                      // split-K factor for the S@Xf GEMM
#define KCHUNK (NN / SK)

// ---------------- scratch (device globals; no allocations allowed) -------------
__device__ float g_L[(size_t)NN * NN];        // logits -> CSR values (in place)
__device__ int   g_Aidx[(size_t)NN * NN];     // CSR column indices
__device__ int   g_Annz[NN];                  // CSR nnz per row
__device__ float g_q[NN * DA];
__device__ float g_k[NN * DA];
__device__ float g_t[NN * DA];
__device__ float g_Xf[NN * DD];
__device__ float g_Xf2[NN * DD];
__device__ float g_Xa[NN * DD];
__device__ float g_Xa2[NN * DD];
__device__ float g_Z[NN * DD];
__device__ float g_rinv[NN];

// ---------------- block reductions (256 threads, broadcast result) -------------
__device__ __forceinline__ float blk_sum(float x, float* sm) {
    #pragma unroll
    for (int o = 16; o > 0; o >>= 1) x += __shfl_xor_sync(0xffffffffu, x, o);
    int w = threadIdx.x >> 5;
    __syncthreads();
    if ((threadIdx.x & 31) == 0) sm[w] = x;
    __syncthreads();
    float r = 0.f;
    #pragma unroll
    for (int i = 0; i < 8; i++) r += sm[i];
    return r;
}

__device__ __forceinline__ float blk_max(float x, float* sm) {
    #pragma unroll
    for (int o = 16; o > 0; o >>= 1) x = fmaxf(x, __shfl_xor_sync(0xffffffffu, x, o));
    int w = threadIdx.x >> 5;
    __syncthreads();
    if ((threadIdx.x & 31) == 0) sm[w] = x;
    __syncthreads();
    float r = -INFINITY;
    #pragma unroll
    for (int i = 0; i < 8; i++) r = fmaxf(r, sm[i]);
    return r;
}

__device__ __forceinline__ double blk_sum_d(double x, double* smd) {
    #pragma unroll
    for (int o = 16; o > 0; o >>= 1) x += __shfl_xor_sync(0xffffffffu, x, o);
    int w = threadIdx.x >> 5;
    __syncthreads();
    if ((threadIdx.x & 31) == 0) smd[w] = x;
    __syncthreads();
    double r = 0.0;
    #pragma unroll
    for (int i = 0; i < 8; i++) r += smd[i];
    return r;
}

// ---------------- row sums of S -> rinv = 1/(1 + sum) --------------------------
__global__ void rowsum_kernel(const float* __restrict__ S, float* __restrict__ rinv) {
    __shared__ float sm[8];
    int row = blockIdx.x;
    const float* Sr = S + (size_t)row * NN;
    float s = 0.f;
    for (int j = threadIdx.x; j < NN; j += 256) s += Sr[j];
    s = blk_sum(s, sm);
    if (threadIdx.x == 0) rinv[row] = 1.0f / (s + 1.0f);
}

// ---------------- fp32 SIMT GEMM, double-buffered smem, 2 CTA/SM ---------------
// Attention-chain GEMMs: strict ascending-k single-accumulator (validated, do
// not perturb). TRANSB=1: B is [N,K] (NT). TRANSB=0: B is [K,N] (NN).
// EPI: 0 -> C = acc ; 2 -> C += acc
#define BM 128
#define BN 128
#define BK 16
#define SPAD 4

template<int TRANSB, int EPI>
__global__ void __launch_bounds__(256, 2) gemm_kernel(
    const float* __restrict__ A, const float* __restrict__ B, float* __restrict__ C,
    int M, int N, int K,
    const float* __restrict__ Xadd, const float* __restrict__ rscale)
{
    __shared__ float As[2][BK][BM + SPAD];
    __shared__ float Bs[2][BK][BN + SPAD];

    const int tid = threadIdx.x;
    const int m0 = blockIdx.y * BM;
    const int n0 = blockIdx.x * BN;
    const int tx = tid & 15;
    const int ty = tid >> 4;

    const int ar = (tid >> 2);
    const int ac = (tid & 3) * 4;
    const int br_t = (tid >> 2);
    const int bc_t = (tid & 3) * 4;
    const int br_n = (tid >> 5);
    const int bc_n = (tid & 31) * 4;

    float acc[8][8];
    #pragma unroll
    for (int i = 0; i < 8; i++)
        #pragma unroll
        for (int j = 0; j < 8; j++) acc[i][j] = 0.f;

    const int T = K / BK;
    float4 pa[2], pb[2];

    {
        const int k0 = 0;
        #pragma unroll
        for (int it = 0; it < 2; it++)
            pa[it] = *(const float4*)(A + (size_t)(m0 + ar + it * 64) * K + k0 + ac);
        if (TRANSB) {
            #pragma unroll
            for (int it = 0; it < 2; it++) {
                int r = br_t + it * 64;
                pb[it] = make_float4(0.f, 0.f, 0.f, 0.f);
                if (n0 + r < N)
                    pb[it] = *(const float4*)(B + (size_t)(n0 + r) * K + k0 + bc_t);
            }
        } else {
            #pragma unroll
            for (int it = 0; it < 2; it++) {
                int r = br_n + it * 8;
                pb[it] = make_float4(0.f, 0.f, 0.f, 0.f);
                if (n0 + bc_n < N)
                    pb[it] = *(const float4*)(B + (size_t)(k0 + r) * N + n0 + bc_n);
            }
        }
    }
    {
        #pragma unroll
        for (int it = 0; it < 2; it++) {
            int r = ar + it * 64;
            As[0][ac + 0][r] = pa[it].x; As[0][ac + 1][r] = pa[it].y;
            As[0][ac + 2][r] = pa[it].z; As[0][ac + 3][r] = pa[it].w;
        }
        if (TRANSB) {
            #pragma unroll
            for (int it = 0; it < 2; it++) {
                int r = br_t + it * 64;
                Bs[0][bc_t + 0][r] = pb[it].x; Bs[0][bc_t + 1][r] = pb[it].y;
                Bs[0][bc_t + 2][r] = pb[it].z; Bs[0][bc_t + 3][r] = pb[it].w;
            }
        } else {
            #pragma unroll
            for (int it = 0; it < 2; it++)
                *(float4*)&Bs[0][br_n + it * 8][bc_n] = pb[it];
        }
    }
    __syncthreads();

    for (int t = 0; t < T; t++) {
        const int cur = t & 1;
        const int nxt = cur ^ 1;

        if (t + 1 < T) {
            const int k0 = (t + 1) * BK;
            #pragma unroll
            for (int it = 0; it < 2; it++)
                pa[it] = *(const float4*)(A + (size_t)(m0 + ar + it * 64) * K + k0 + ac);
            if (TRANSB) {
                #pragma unroll
                for (int it = 0; it < 2; it++) {
                    int r = br_t + it * 64;
                    pb[it] = make_float4(0.f, 0.f, 0.f, 0.f);
                    if (n0 + r < N)
                        pb[it] = *(const float4*)(B + (size_t)(n0 + r) * K + k0 + bc_t);
                }
            } else {
                #pragma unroll
                for (int it = 0; it < 2; it++) {
                    int r = br_n + it * 8;
                    pb[it] = make_float4(0.f, 0.f, 0.f, 0.f);
                    if (n0 + bc_n < N)
                        pb[it] = *(const float4*)(B + (size_t)(k0 + r) * N + n0 + bc_n);
                }
            }
        }

        #pragma unroll
        for (int k = 0; k < BK; k++) {
            float a[8], b[8];
            *(float4*)&a[0] = *(const float4*)&As[cur][k][ty * 8];
            *(float4*)&a[4] = *(const float4*)&As[cur][k][ty * 8 + 4];
            *(float4*)&b[0] = *(const float4*)&Bs[cur][k][tx * 8];
            *(float4*)&b[4] = *(const float4*)&Bs[cur][k][tx * 8 + 4];
            #pragma unroll
            for (int i = 0; i < 8; i++)
                #pragma unroll
                for (int j = 0; j < 8; j++)
                    acc[i][j] = fmaf(a[i], b[j], acc[i][j]);
        }

        if (t + 1 < T) {
            #pragma unroll
            for (int it = 0; it < 2; it++) {
                int r = ar + it * 64;
                As[nxt][ac + 0][r] = pa[it].x; As[nxt][ac + 1][r] = pa[it].y;
                As[nxt][ac + 2][r] = pa[it].z; As[nxt][ac + 3][r] = pa[it].w;
            }
            if (TRANSB) {
                #pragma unroll
                for (int it = 0; it < 2; it++) {
                    int r = br_t + it * 64;
                    Bs[nxt][bc_t + 0][r] = pb[it].x; Bs[nxt][bc_t + 1][r] = pb[it].y;
                    Bs[nxt][bc_t + 2][r] = pb[it].z; Bs[nxt][bc_t + 3][r] = pb[it].w;
                }
            } else {
                #pragma unroll
                for (int it = 0; it < 2; it++)
                    *(float4*)&Bs[nxt][br_n + it * 8][bc_n] = pb[it];
            }
        }
        __syncthreads();
    }

    #pragma unroll
    for (int i = 0; i < 8; i++) {
        int row = m0 + ty * 8 + i;
        #pragma unroll
        for (int jj = 0; jj < 2; jj++) {
            int col = n0 + tx * 8 + jj * 4;
            if (col < N) {
                size_t idx = (size_t)row * N + col;
                float4 v;
                v.x = acc[i][jj * 4 + 0]; v.y = acc[i][jj * 4 + 1];
                v.z = acc[i][jj * 4 + 2]; v.w = acc[i][jj * 4 + 3];
                if (EPI == 2) {
                    float4 cv = *(const float4*)(C + idx);
                    v.x += cv.x; v.y += cv.y; v.z += cv.z; v.w += cv.w;
                }
                *(float4*)(C + idx) = v;
            }
        }
    }
}

// ---------------- split-K fp32 GEMM for S @ Xf (Xf path: order-free) -----------
// grid (N/BN, M/BM, SK); each z-slice accumulates K range [z*KCHUNK,(z+1)*KCHUNK)
// and atomicAdds its partial into C (pre-zeroed). Accumulation order differs
// from the reference but the Xf path is linear -- ~1e-6 level, no decisions.
__global__ void __launch_bounds__(256, 2) gemm_splitk_kernel(
    const float* __restrict__ A, const float* __restrict__ B, float* __restrict__ C)
{
    __shared__ float As[2][BK][BM + SPAD];
    __shared__ float Bs[2][BK][BN + SPAD];

    const int tid = threadIdx.x;
    const int m0 = blockIdx.y * BM;
    const int n0 = blockIdx.x * BN;
    const int kbase = blockIdx.z * KCHUNK;
    const int tx = tid & 15;
    const int ty = tid >> 4;

    const int ar = (tid >> 2);
    const int ac = (tid & 3) * 4;
    const int br_n = (tid >> 5);
    const int bc_n = (tid & 31) * 4;

    float acc[8][8];
    #pragma unroll
    for (int i = 0; i < 8; i++)
        #pragma unroll
        for (int j = 0; j < 8; j++) acc[i][j] = 0.f;

    const int T = KCHUNK / BK;
    float4 pa[2], pb[2];

    {
        const int k0 = kbase;
        #pragma unroll
        for (int it = 0; it < 2; it++)
            pa[it] = *(const float4*)(A + (size_t)(m0 + ar + it * 64) * NN + k0 + ac);
        #pragma unroll
        for (int it = 0; it < 2; it++)
            pb[it] = *(const float4*)(B + (size_t)(k0 + br_n + it * 8) * DD + n0 + bc_n);
    }
    {
        #pragma unroll
        for (int it = 0; it < 2; it++) {
            int r = ar + it * 64;
            As[0][ac + 0][r] = pa[it].x; As[0][ac + 1][r] = pa[it].y;
            As[0][ac + 2][r] = pa[it].z; As[0][ac + 3][r] = pa[it].w;
        }
        #pragma unroll
        for (int it = 0; it < 2; it++)
            *(float4*)&Bs[0][br_n + it * 8][bc_n] = pb[it];
    }
    __syncthreads();

    for (int t = 0; t < T; t++) {
        const int cur = t & 1;
        const int nxt = cur ^ 1;

        if (t + 1 < T) {
            const int k0 = kbase + (t + 1) * BK;
            #pragma unroll
            for (int it = 0; it < 2; it++)
                pa[it] = *(const float4*)(A + (size_t)(m0 + ar + it * 64) * NN + k0 + ac);
            #pragma unroll
            for (int it = 0; it < 2; it++)
                pb[it] = *(const float4*)(B + (size_t)(k0 + br_n + it * 8) * DD + n0 + bc_n);
        }

        #pragma unroll
        for (int k = 0; k < BK; k++) {
            float a[8], b[8];
            *(float4*)&a[0] = *(const float4*)&As[cur][k][ty * 8];
            *(float4*)&a[4] = *(const float4*)&As[cur][k][ty * 8 + 4];
            *(float4*)&b[0] = *(const float4*)&Bs[cur][k][tx * 8];
            *(float4*)&b[4] = *(const float4*)&Bs[cur][k][tx * 8 + 4];
            #pragma unroll
            for (int i = 0; i < 8; i++)
                #pragma unroll
                for (int j = 0; j < 8; j++)
                    acc[i][j] = fmaf(a[i], b[j], acc[i][j]);
        }

        if (t + 1 < T) {
            #pragma unroll
            for (int it = 0; it < 2; it++) {
                int r = ar + it * 64;
                As[nxt][ac + 0][r] = pa[it].x; As[nxt][ac + 1][r] = pa[it].y;
                As[nxt][ac + 2][r] = pa[it].z; As[nxt][ac + 3][r] = pa[it].w;
            }
            #pragma unroll
            for (int it = 0; it < 2; it++)
                *(float4*)&Bs[nxt][br_n + it * 8][bc_n] = pb[it];
        }
        __syncthreads();
    }

    #pragma unroll
    for (int i = 0; i < 8; i++) {
        int row = m0 + ty * 8 + i;
        #pragma unroll
        for (int j = 0; j < 8; j++) {
            int col = n0 + tx * 8 + j;
            if (col < DD)
                atomicAdd(C + (size_t)row * DD + col, acc[i][j]);
        }
    }
}

// Xf2 = rinv[row] * (Xf2_acc + Xf)
__global__ void __launch_bounds__(256) scale_add_kernel(
    float* __restrict__ Xf2, const float* __restrict__ Xf,
    const float* __restrict__ rinv)
{
    int row = blockIdx.x;
    int c = threadIdx.x;
    size_t idx = (size_t)row * DD + c;
    Xf2[idx] = rinv[row] * (Xf2[idx] + Xf[idx]);
}

// ---------------- top-p -> CSR (literal reference semantics) -------------------
// expf instead of exp(double): R5 vs R9 produced bit-identical kept sets under
// both exps, so decisions are unchanged; values move ~1 ulp (linear path).
// Rest identical: fp32 div probs, u64 keys, descending bitonic over a provable
// candidate superset, fp32 cumsum walk, double kept-mass, ascending-index CSR.
__global__ void __launch_bounds__(256) topp_kernel(float* __restrict__ L,
                                                   int* __restrict__ Aidx,
                                                   int* __restrict__ Annz) {
    extern __shared__ unsigned long long key[];   // capacity 8192 (64KB)
    __shared__ float sm[8];
    __shared__ double smd[8];
    __shared__ int s_cnt;
    __shared__ int s_jstop;
    __shared__ float s_inv;

    const int row = blockIdx.x;
    const int tid = threadIdx.x;
    float* Lr = L + (size_t)row * NN;

    float v[32];
    #pragma unroll
    for (int i = 0; i < 32; i++) v[i] = Lr[i * 256 + tid];

    float m = -INFINITY;
    #pragma unroll
    for (int i = 0; i < 32; i++) m = fmaxf(m, v[i]);
    m = blk_max(m, sm);

    double zloc = 0.0;
    #pragma unroll
    for (int i = 0; i < 32; i++) {
        v[i] = expf(v[i] - m);
        zloc += (double)v[i];
    }
    double Zd = blk_sum_d(zloc, smd);
    const float Zf = (float)Zd;

    float ploc = 0.f;
    #pragma unroll
    for (int i = 0; i < 32; i++) {
        v[i] = __fdiv_rn(v[i], Zf);
        ploc += v[i];
    }
    const float Ptot = blk_sum(ploc, sm);
    const float target = 0.92f * Ptot;   // 2% slack over the 0.9 walk target

    // largest u with  sum{p > float(u)} >= target  (superset guarantee)
    unsigned lo = 0u, hi = 0x3F800000u;
    while (lo < hi) {
        unsigned mid = (lo + hi + 1u) >> 1;
        float t = __uint_as_float(mid);
        float s = 0.f;
        #pragma unroll
        for (int i = 0; i < 32; i++) s += (v[i] > t) ? v[i] : 0.f;
        s = blk_sum(s, sm);
        if (s >= target) lo = mid; else hi = mid - 1u;
    }
    const float thr = __uint_as_float(lo);

    if (tid == 0) s_cnt = 0;
    __syncthreads();
    #pragma unroll
    for (int i = 0; i < 32; i++) {
        if (v[i] >= thr) {
            int idx = i * 256 + tid;
            int slot = atomicAdd(&s_cnt, 1);
            key[slot] = ((unsigned long long)__float_as_uint(v[i]) << 32)
                      | (unsigned long long)(0xFFFFFFFFu - (unsigned)idx);
        }
    }
    __syncthreads();
    const int cnt = s_cnt;

    int C2 = 1;
    while (C2 < cnt) C2 <<= 1;
    for (int i = cnt + tid; i < C2; i += 256) key[i] = 0ull;  // pad: sorts last
    __syncthreads();

    // bitonic sort, DESCENDING (prob-major, ascending-index ties)
    for (int k2 = 2; k2 <= C2; k2 <<= 1) {
        for (int j = k2 >> 1; j > 0; j >>= 1) {
            for (int base = 0; base < C2; base += 256) {
                int i = base + tid;
                if (i < C2) {
                    int ij = i ^ j;
                    if (ij > i) {
                        unsigned long long a = key[i];
                        unsigned long long b = key[ij];
                        bool descBlock = ((i & k2) == 0);
                        if (descBlock ? (a < b) : (a > b)) {
                            key[i] = b;
                            key[ij] = a;
                        }
                    }
                }
            }
            __syncthreads();
        }
    }

    // sequential fp32 cumsum walk (bitwise-faithful), early exit
    if (tid == 0) {
        float cs = 0.f;
        int j = 0;
        for (; j < cnt; j++) {
            float p = __uint_as_float((unsigned)(key[j] >> 32));
            cs = __fadd_rn(cs, p);
            float excl = __fsub_rn(cs, p);
            if (!(excl < 0.9f)) break;
        }
        s_jstop = j;                        // kept = sorted positions [0, j)
    }
    __syncthreads();
    const int jstop = s_jstop;

    // kept mass (double) -> inv
    {
        double ks = 0.0;
        for (int p0 = tid; p0 < jstop; p0 += 256)
            ks += (double)__uint_as_float((unsigned)(key[p0] >> 32));
        double ksd = blk_sum_d(ks, smd);
        if (tid == 0) s_inv = (float)(1.0 / fmax(ksd, 1e-12));
    }
    __syncthreads();
    const float inv = s_inv;

    // rekey kept entries as [idx | pbits] for ascending-index sort
    for (int p0 = tid; p0 < jstop; p0 += 256) {
        unsigned long long kk = key[p0];
        unsigned orig = 0xFFFFFFFFu - (unsigned)(kk & 0xFFFFFFFFull);
        unsigned pbits = (unsigned)(kk >> 32);
        key[p0] = ((unsigned long long)orig << 32) | (unsigned long long)pbits;
    }
    __syncthreads();

    int K2 = 1;
    while (K2 < jstop) K2 <<= 1;
    if (K2 < 2) K2 = 2;
    for (int i = jstop + tid; i < K2; i += 256) key[i] = 0xFFFFFFFFFFFFFFFFull;
    __syncthreads();

    // bitonic sort ASCENDING by index
    for (int k2 = 2; k2 <= K2; k2 <<= 1) {
        for (int j = k2 >> 1; j > 0; j >>= 1) {
            for (int base = 0; base < K2; base += 256) {
                int i = base + tid;
                if (i < K2) {
                    int ij = i ^ j;
                    if (ij > i) {
                        unsigned long long a = key[i];
                        unsigned long long b = key[ij];
                        bool ascBlock = ((i & k2) == 0);
                        if (ascBlock ? (a > b) : (a < b)) {
                            key[i] = b;
                            key[ij] = a;
                        }
                    }
                }
            }
            __syncthreads();
        }
    }

    // emit CSR: columns ascending, values = p * inv
    int* Ar = Aidx + (size_t)row * NN;
    for (int p0 = tid; p0 < jstop; p0 += 256) {
        unsigned long long kk = key[p0];
        Ar[p0] = (int)(kk >> 32);
        Lr[p0] = __uint_as_float((unsigned)(kk & 0xFFFFFFFFull)) * inv;
    }
    if (tid == 0) Annz[row] = jstop;
}

// ---------------- sparse A @ Xa  (bitwise == dense ascending-k GEMM) -----------
__global__ void __launch_bounds__(256) spmm_kernel(
    const float* __restrict__ Aval, const int* __restrict__ Aidx,
    const int* __restrict__ Annz,
    const float* __restrict__ Xa, float* __restrict__ Xa2)
{
    const int row = blockIdx.x;
    const int c = threadIdx.x;
    const float* val = Aval + (size_t)row * NN;
    const int* col = Aidx + (size_t)row * NN;
    const int nnz = Annz[row];

    float acc = 0.f;
    int j = 0;
    for (; j + 4 <= nnz; j += 4) {
        float v0 = val[j + 0]; int c0 = col[j + 0];
        float v1 = val[j + 1]; int c1 = col[j + 1];
        float v2 = val[j + 2]; int c2 = col[j + 2];
        float v3 = val[j + 3]; int c3 = col[j + 3];
        acc = fmaf(v0, Xa[(size_t)c0 * DD + c], acc);
        acc = fmaf(v1, Xa[(size_t)c1 * DD + c], acc);
        acc = fmaf(v2, Xa[(size_t)c2 * DD + c], acc);
        acc = fmaf(v3, Xa[(size_t)c3 * DD + c], acc);
    }
    for (; j < nnz; j++)
        acc = fmaf(val[j], Xa[(size_t)col[j] * DD + c], acc);

    Xa2[(size_t)row * DD + c] = acc;
}

// ---------------- final residual + layernorm -----------------------------------
__global__ void __launch_bounds__(256) ln_kernel(
    const float* __restrict__ X, const float* __restrict__ Z,
    const float* __restrict__ g, const float* __restrict__ b,
    float* __restrict__ out)
{
    __shared__ float sm[8];
    int row = blockIdx.x;
    int c = threadIdx.x;
    size_t idx = (size_t)row * DD + c;
    float h = X[idx] + Z[idx];
    float s1 = blk_sum(h, sm);
    float mu = s1 * (1.0f / DD);
    float d = h - mu;
    float s2 = blk_sum(d * d, sm);
    float var = s2 * (1.0f / DD);
    out[idx] = d * rsqrtf(var + 1e-5f) * g[c] + b[c];
}

// ---------------- host orchestration -------------------------------------------
extern "C" void kernel_launch(void* const* d_in, const int* in_sizes, int n_in,
                              void* d_out, int out_size) {
    const float* X   = (const float*)d_in[0];
    const float* S   = (const float*)d_in[1];
    const float* W1  = (const float*)d_in[2];
    const float* W2  = (const float*)d_in[3];
    const float* W3  = (const float*)d_in[4];
    const float* U1  = (const float*)d_in[5];
    const float* U2  = (const float*)d_in[6];
    const float* lng = (const float*)d_in[7];
    const float* lnb = (const float*)d_in[8];
    float* out = (float*)d_out;

    float *L, *q, *k, *t, *Xf, *Xf2, *Xa, *Xa2, *Z, *rinv;
    int *Aidx, *Annz;
    cudaGetSymbolAddress((void**)&L,    g_L);
    cudaGetSymbolAddress((void**)&Aidx, g_Aidx);
    cudaGetSymbolAddress((void**)&Annz, g_Annz);
    cudaGetSymbolAddress((void**)&q,    g_q);
    cudaGetSymbolAddress((void**)&k,    g_k);
    cudaGetSymbolAddress((void**)&t,    g_t);
    cudaGetSymbolAddress((void**)&Xf,   g_Xf);
    cudaGetSymbolAddress((void**)&Xf2,  g_Xf2);
    cudaGetSymbolAddress((void**)&Xa,   g_Xa);
    cudaGetSymbolAddress((void**)&Xa2,  g_Xa2);
    cudaGetSymbolAddress((void**)&Z,    g_Z);
    cudaGetSymbolAddress((void**)&rinv, g_rinv);

    static bool attr_set = false;
    if (!attr_set) {
        cudaFuncSetAttribute(topp_kernel,
                             cudaFuncAttributeMaxDynamicSharedMemorySize,
                             NN * sizeof(unsigned long long));
        attr_set = true;
    }

    const size_t XB = (size_t)NN * DD * sizeof(float);

    rowsum_kernel<<<NN, 256>>>(S, rinv);
    cudaMemcpyAsync(Xf, X, XB, cudaMemcpyDeviceToDevice);
    cudaMemcpyAsync(Xa, X, XB, cudaMemcpyDeviceToDevice);
    cudaMemsetAsync(Z, 0, XB);

    for (int n = 0; n < 2; n++) {
        // q = (Xa @ W1^T) @ W2^T ; k = Xa @ W3^T  (attention chain: untouched)
        gemm_kernel<1, 0><<<dim3(1, NN / BM), 256>>>(Xa, W1, t, NN, DA, DD, nullptr, nullptr);
        gemm_kernel<1, 0><<<dim3(1, NN / BM), 256>>>(t,  W2, q, NN, DA, DA, nullptr, nullptr);
        gemm_kernel<1, 0><<<dim3(1, NN / BM), 256>>>(Xa, W3, k, NN, DA, DD, nullptr, nullptr);

        // logits = q @ k^T  (attention chain: untouched)
        gemm_kernel<1, 0><<<dim3(NN / BN, NN / BM), 256>>>(q, k, L, NN, NN, DA, nullptr, nullptr);

        // softmax + top-p (literal reference semantics, expf) -> CSR(A)
        topp_kernel<<<NN, 256, NN * sizeof(unsigned long long)>>>(L, Aidx, Annz);

        // Xa2 = A @ Xa  (sparse; bitwise == dense ascending-k GEMM)
        spmm_kernel<<<NN, 256>>>(L, Aidx, Annz, Xa, Xa2);

        // Xf2 = rinv * (S @ Xf + Xf)  via split-K + atomics (Xf path: order-free)
        cudaMemsetAsync(Xf2, 0, XB);
        gemm_splitk_kernel<<<dim3(DD / BN, NN / BM, SK), 256>>>(S, Xf, Xf2);
        scale_add_kernel<<<NN, 256>>>(Xf2, Xf, rinv);

        // Z += Xf2 @ U1[n]^T + Xa2 @ U2[n]^T
        gemm_kernel<1, 2><<<dim3(DD / BN, NN / BM), 256>>>(Xf2, U1 + (size_t)n * DD * DD, Z, NN, DD, DD, nullptr, nullptr);
        gemm_kernel<1, 2><<<dim3(DD / BN, NN / BM), 256>>>(Xa2, U2 + (size_t)n * DD * DD, Z, NN, DD, DD, nullptr, nullptr);

        { float* tmp = Xf; Xf = Xf2; Xf2 = tmp; }
        { float* tmp = Xa; Xa = Xa2; Xa2 = tmp; }
    }

    ln_kernel<<<NN, 256>>>(X, Z, lng, lnb, out);
}